// round 5
// baseline (speedup 1.0000x reference)
#include <cuda_runtime.h>

#define FULLMASK 0xffffffffu

// ---------------- scratch (__device__ globals; no allocation allowed) ----------------
__device__ __align__(16) unsigned g_X1[6*784*40];      // packed bip(image, rm_in1)
__device__ __align__(16) unsigned g_W1[6*25*40];       // packed bip(w1, rm_k1)
__device__ __align__(16) unsigned g_W2[16*6*25*40];    // packed bip(w2, rm_k2)
__device__ __align__(16) unsigned g_X2[16*6*144*40];   // packed bip(p1norm, rm_in2)
__device__ __align__(16) unsigned g_SW3[120*256*40];   // [m][n][40]
__device__ __align__(16) unsigned g_SW4[84*120*40];    // [m][n][40]
__device__ __align__(16) unsigned g_SW5[10*84*40];     // [m][n][40]
__device__ __align__(16) unsigned g_X3[256*40];
__device__ __align__(16) unsigned g_X4[120*40];
__device__ __align__(16) unsigned g_X5[84*40];
__device__ int g_pos3[120];
__device__ int g_pos4[84];
__device__ int g_pos5[10];
__device__ float g_c1r[6*576];    // relu(c1), (6,24,24)
__device__ float g_P1[864];       // pool1 (6,12,12) un-normalized
__device__ float g_c2r[16*64];    // relu(c2), (16,8,8)
__device__ float g_P2[256];       // pool2 (16,4,4) un-normalized
__device__ float g_f1[120];       // relu(fc3) un-normalized
__device__ float g_f2[84];        // relu(fc4) un-normalized
__device__ unsigned g_mm[8];      // bit-punned nonneg float min/max: [0,1]=pool1 [2,3]=pool2 [4,5]=fc3 [6,7]=fc4

// ---------------- helpers ----------------

// Pack one bitstream row: 1280 floats -> 40 uint32 words. bit j of word wd = ((v+1)*0.5 > rm[wd*32+j]).
__device__ __forceinline__ void pack_row(const float* __restrict__ src, float thr,
                                         unsigned* __restrict__ dst, int lane) {
#pragma unroll
    for (int wd = 0; wd < 40; wd += 4) {
        float v0 = src[(wd+0)*32 + lane];
        float v1 = src[(wd+1)*32 + lane];
        float v2 = src[(wd+2)*32 + lane];
        float v3 = src[(wd+3)*32 + lane];
        unsigned b0 = __ballot_sync(FULLMASK, thr > v0);
        unsigned b1 = __ballot_sync(FULLMASK, thr > v1);
        unsigned b2 = __ballot_sync(FULLMASK, thr > v2);
        unsigned b3 = __ballot_sync(FULLMASK, thr > v3);
        if (lane == 0) *reinterpret_cast<uint4*>(dst + wd) = make_uint4(b0, b1, b2, b3);
    }
}

// Same, but return popcount of the whole row (for bias streams).
__device__ __forceinline__ int pack_row_popc(const float* __restrict__ src, float thr, int lane) {
    int s = 0;
#pragma unroll
    for (int wd = 0; wd < 40; wd += 4) {
        float v0 = src[(wd+0)*32 + lane];
        float v1 = src[(wd+1)*32 + lane];
        float v2 = src[(wd+2)*32 + lane];
        float v3 = src[(wd+3)*32 + lane];
        s += __popc(__ballot_sync(FULLMASK, thr > v0));
        s += __popc(__ballot_sync(FULLMASK, thr > v1));
        s += __popc(__ballot_sync(FULLMASK, thr > v2));
        s += __popc(__ballot_sync(FULLMASK, thr > v3));
    }
    return s;
}

__device__ __forceinline__ float thr_of(float v) {
    return __fmul_rn(__fadd_rn(v, 1.0f), 0.5f);
}

// ---------------- kernels ----------------

__global__ void k_init() {
    int t = threadIdx.x;
    if (t < 8) g_mm[t] = (t & 1) ? 0u : 0x7f800000u;  // min=+inf, max=0 (all values >= 0)
}

// Pack everything available at t=0 that conv1 needs: X1 (24MB), W1, W2.
__global__ void k_pack_static(const float* __restrict__ img, const float* __restrict__ w1,
                              const float* __restrict__ w2,
                              const float* __restrict__ rm_in1, const float* __restrict__ rm_k1,
                              const float* __restrict__ rm_k2) {
    int lane = threadIdx.x & 31;
    int gw = (blockIdx.x * blockDim.x + threadIdx.x) >> 5;
    int nw = (gridDim.x * blockDim.x) >> 5;
    const int R1 = 6*784, R2 = R1 + 6*25, R3 = R2 + 16*6*25;
    for (int row = gw; row < R3; row += nw) {
        if (row < R1) {
            pack_row(rm_in1 + (size_t)row * 1280, thr_of(img[row % 784]), g_X1 + row*40, lane);
        } else if (row < R2) {
            int r = row - R1;
            pack_row(rm_k1 + (size_t)r * 1280, thr_of(w1[r]), g_W1 + r*40, lane);
        } else {
            int r = row - R2;
            pack_row(rm_k2 + (size_t)r * 1280, thr_of(w2[r]), g_W2 + r*40, lane);
        }
    }
}

// conv1: one warp per (o, window). 25 taps x 40 words XOR/popc.
__global__ void k_conv1(const float* __restrict__ b1) {
    int lane = threadIdx.x & 31;
    int wid = (blockIdx.x * blockDim.x + threadIdx.x) >> 5;
    if (wid >= 6*576) return;
    int o = wid / 576, w = wid % 576;
    int r = w / 24, c = w % 24;
    const unsigned* xb = g_X1 + o*784*40;
    const unsigned* wb = g_W1 + o*25*40;
    int ham = 0;
#pragma unroll
    for (int k = 0; k < 25; ++k) {
        int n = (r + k/5)*28 + (c + k%5);
        const unsigned* xr = xb + n*40;
        const unsigned* wr = wb + k*40;
        for (int wd = lane; wd < 40; wd += 32) ham += __popc(xr[wd] ^ wr[wd]);
    }
#pragma unroll
    for (int off = 16; off; off >>= 1) ham += __shfl_down_sync(FULLMASK, ham, off);
    if (lane == 0) {
        // count = 32000 - H (exact int). XLA rewrites x/32000 -> x*(1/32000).
        float cnt = (float)(32000 - ham);
        float q = __fmul_rn(cnt, (1.0f/32000.0f));
        float y = __fsub_rn(__fmul_rn(2.0f, q), 1.0f);
        float v = __fadd_rn(__fmul_rn(y, 25.0f), b1[o]);
        g_c1r[o*576 + w] = fmaxf(v, 0.0f);
    }
}

__global__ void k_pool1() {  // <<<1,864>>>  (6,24,24)->(6,12,12) max2x2, record min/max
    int t = threadIdx.x;
    int o = t / 144, rem = t % 144, pr = rem / 12, pc = rem % 12;
    const float* base = g_c1r + o*576 + (2*pr)*24 + 2*pc;
    float m = fmaxf(fmaxf(base[0], base[1]), fmaxf(base[24], base[25]));
    g_P1[t] = m;
    atomicMin(&g_mm[0], __float_as_uint(m));
    atomicMax(&g_mm[1], __float_as_uint(m));
}

// The big one: packs X2 (71MB rm_in2) + SW3/SW4/SW5 (215MB) + bias streams, ~285MB HBM.
__global__ void k_pack_big(const float* __restrict__ rm_in2,
                           const float* __restrict__ wfc3, const float* __restrict__ rm_w3,
                           const float* __restrict__ wfc4, const float* __restrict__ rm_w4,
                           const float* __restrict__ wfc5, const float* __restrict__ rm_w5,
                           const float* __restrict__ bfc3, const float* __restrict__ rm_b3,
                           const float* __restrict__ bfc4, const float* __restrict__ rm_b4,
                           const float* __restrict__ bfc5, const float* __restrict__ rm_b5) {
    int lane = threadIdx.x & 31;
    int gw = (blockIdx.x * blockDim.x + threadIdx.x) >> 5;
    int nw = (gridDim.x * blockDim.x) >> 5;
    const int RX2 = 16*6*144;            // 13824
    const int RS3 = RX2 + 256*120;       // 44544
    const int RS4 = RS3 + 120*84;        // 54624
    const int RS5 = RS4 + 84*10;         // 55464
    const int RB3 = RS5 + 120;
    const int RB4 = RB3 + 84;
    const int RB5 = RB4 + 10;
    float mn = __uint_as_float(g_mm[0]);
    float mx = __uint_as_float(g_mm[1]);
    float den = mx - mn;
    for (int row = gw; row < RB5; row += nw) {
        if (row < RX2) {
            float p = g_P1[row % 864];                       // row = (o*6+i)*144+n; mod 864 = i*144+n
            float pv = __fdiv_rn(p - mn, den);               // norm01 (runtime denom: stays true div)
            pack_row(rm_in2 + (size_t)row * 1280, thr_of(pv), g_X2 + row*40, lane);
        } else if (row < RS3) {
            int r = row - RX2; int n = r / 120, m = r % 120; // rm_w3 is [n][m][l]
            pack_row(rm_w3 + (size_t)r * 1280, thr_of(wfc3[r]), g_SW3 + (m*256 + n)*40, lane);
        } else if (row < RS4) {
            int r = row - RS3; int n = r / 84, m = r % 84;
            pack_row(rm_w4 + (size_t)r * 1280, thr_of(wfc4[r]), g_SW4 + (m*120 + n)*40, lane);
        } else if (row < RS5) {
            int r = row - RS4; int n = r / 10, m = r % 10;
            pack_row(rm_w5 + (size_t)r * 1280, thr_of(wfc5[r]), g_SW5 + (m*84 + n)*40, lane);
        } else if (row < RB3) {
            int r = row - RS5;
            int s = pack_row_popc(rm_b3 + (size_t)r * 1280, thr_of(bfc3[r]), lane);
            if (lane == 0) g_pos3[r] = s;
        } else if (row < RB4) {
            int r = row - RB3;
            int s = pack_row_popc(rm_b4 + (size_t)r * 1280, thr_of(bfc4[r]), lane);
            if (lane == 0) g_pos4[r] = s;
        } else {
            int r = row - RB4;
            int s = pack_row_popc(rm_b5 + (size_t)r * 1280, thr_of(bfc5[r]), lane);
            if (lane == 0) g_pos5[r] = s;
        }
    }
}

// conv2: one 256-thread block per (o, window); sum over i(6)*k(25)*40 words.
__global__ void k_conv2(const float* __restrict__ b2) {
    __shared__ int sh[256];
    int o = blockIdx.x >> 6, w = blockIdx.x & 63;
    int r = w >> 3, c = w & 7;
    int ham = 0;
    for (int t = threadIdx.x; t < 6000; t += 256) {
        int wd = t % 40; int rest = t / 40; int k = rest % 25; int i = rest / 25;
        int n = (r + k/5)*12 + (c + k%5);
        ham += __popc(g_X2[((o*6 + i)*144 + n)*40 + wd] ^ g_W2[((o*6 + i)*25 + k)*40 + wd]);
    }
    sh[threadIdx.x] = ham; __syncthreads();
    for (int s = 128; s; s >>= 1) {
        if (threadIdx.x < s) sh[threadIdx.x] += sh[threadIdx.x + s];
        __syncthreads();
    }
    if (threadIdx.x == 0) {
        float cnt = (float)(192000 - sh[0]);
        float q = __fmul_rn(cnt, (1.0f/192000.0f));
        float y = __fsub_rn(__fmul_rn(2.0f, q), 1.0f);
        float v = __fadd_rn(__fmul_rn(y, 150.0f), b2[o]);
        g_c2r[blockIdx.x] = fmaxf(v, 0.0f);
    }
}

__global__ void k_pool2() {  // <<<1,256>>>  (16,8,8)->(16,4,4)
    int t = threadIdx.x;
    int o = t / 16, rem = t % 16, pr = rem / 4, pc = rem % 4;
    const float* base = g_c2r + o*64 + (2*pr)*8 + 2*pc;
    float m = fmaxf(fmaxf(base[0], base[1]), fmaxf(base[8], base[9]));
    g_P2[t] = m;
    atomicMin(&g_mm[2], __float_as_uint(m));
    atomicMax(&g_mm[3], __float_as_uint(m));
}

// Pack activation streams for FC layers. sel: 0=X3(P2,mm2) 1=X4(f1,mm4) 2=X5(f2,mm6)
__global__ void k_packx(const float* __restrict__ rm, int nrows, int sel) {
    int lane = threadIdx.x & 31;
    int gw = (blockIdx.x * blockDim.x + threadIdx.x) >> 5;
    int nw = (gridDim.x * blockDim.x) >> 5;
    const float* vals; unsigned* dst; int mmi;
    if (sel == 0)      { vals = g_P2; dst = g_X3; mmi = 2; }
    else if (sel == 1) { vals = g_f1; dst = g_X4; mmi = 4; }
    else               { vals = g_f2; dst = g_X5; mmi = 6; }
    float mn = __uint_as_float(g_mm[mmi]);
    float mx = __uint_as_float(g_mm[mmi + 1]);
    float den = mx - mn;
    for (int row = gw; row < nrows; row += nw) {
        float pv = __fdiv_rn(vals[row] - mn, den);
        pack_row(rm + (size_t)row * 1280, thr_of(pv), dst + row*40, lane);
    }
}

__global__ void k_fc3() {  // <<<120,256>>>
    __shared__ int sh[256];
    int m = blockIdx.x, t = threadIdx.x;
    const unsigned* xr = g_X3 + t*40;
    const unsigned* sr = g_SW3 + (m*256 + t)*40;
    int h = 0;
#pragma unroll
    for (int wd = 0; wd < 40; ++wd) h += __popc(xr[wd] ^ sr[wd]);
    sh[t] = h; __syncthreads();
    for (int s = 128; s; s >>= 1) { if (t < s) sh[t] += sh[t + s]; __syncthreads(); }
    if (t == 0) {
        float cnt = (float)(327680 - sh[0] + g_pos3[m]);   // N*L - H + pos
        float q = __fmul_rn(cnt, (1.0f/328960.0f));        // nacc*L = 257*1280
        float out = __fmul_rn(__fsub_rn(__fmul_rn(2.0f, q), 1.0f), 257.0f);
        float rv = fmaxf(out, 0.0f);
        g_f1[m] = rv;
        atomicMin(&g_mm[4], __float_as_uint(rv));
        atomicMax(&g_mm[5], __float_as_uint(rv));
    }
}

__global__ void k_fc4() {  // <<<84,128>>>
    __shared__ int sh[128];
    int m = blockIdx.x, t = threadIdx.x;
    int h = 0;
    if (t < 120) {
        const unsigned* xr = g_X4 + t*40;
        const unsigned* sr = g_SW4 + (m*120 + t)*40;
#pragma unroll
        for (int wd = 0; wd < 40; ++wd) h += __popc(xr[wd] ^ sr[wd]);
    }
    sh[t] = h; __syncthreads();
    for (int s = 64; s; s >>= 1) { if (t < s) sh[t] += sh[t + s]; __syncthreads(); }
    if (t == 0) {
        float cnt = (float)(153600 - sh[0] + g_pos4[m]);   // 120*1280 - H + pos
        float q = __fmul_rn(cnt, (1.0f/154880.0f));        // 121*1280
        float out = __fmul_rn(__fsub_rn(__fmul_rn(2.0f, q), 1.0f), 121.0f);
        float rv = fmaxf(out, 0.0f);
        g_f2[m] = rv;
        atomicMin(&g_mm[6], __float_as_uint(rv));
        atomicMax(&g_mm[7], __float_as_uint(rv));
    }
}

__global__ void k_fc5(float* __restrict__ out) {  // <<<10,128>>>
    __shared__ int sh[128];
    int m = blockIdx.x, t = threadIdx.x;
    int h = 0;
    if (t < 84) {
        const unsigned* xr = g_X5 + t*40;
        const unsigned* sr = g_SW5 + (m*84 + t)*40;
#pragma unroll
        for (int wd = 0; wd < 40; ++wd) h += __popc(xr[wd] ^ sr[wd]);
    }
    sh[t] = h; __syncthreads();
    for (int s = 64; s; s >>= 1) { if (t < s) sh[t] += sh[t + s]; __syncthreads(); }
    if (t == 0) {
        float cnt = (float)(107520 - sh[0] + g_pos5[m]);   // 84*1280 - H + pos
        float q = __fmul_rn(cnt, (1.0f/108800.0f));        // 85*1280
        out[m] = __fmul_rn(__fsub_rn(__fmul_rn(2.0f, q), 1.0f), 85.0f);  // no relu/norm on fc5
    }
}

// ---------------- launch ----------------
extern "C" void kernel_launch(void* const* d_in, const int* in_sizes, int n_in,
                              void* d_out, int out_size) {
    const float* img    = (const float*)d_in[0];
    const float* w1     = (const float*)d_in[1];
    const float* b1     = (const float*)d_in[2];
    const float* w2     = (const float*)d_in[3];
    const float* b2     = (const float*)d_in[4];
    const float* wfc3   = (const float*)d_in[5];
    const float* bfc3   = (const float*)d_in[6];
    const float* wfc4   = (const float*)d_in[7];
    const float* bfc4   = (const float*)d_in[8];
    const float* wfc5   = (const float*)d_in[9];
    const float* bfc5   = (const float*)d_in[10];
    const float* rm_in1 = (const float*)d_in[11];
    const float* rm_k1  = (const float*)d_in[12];
    const float* rm_in2 = (const float*)d_in[13];
    const float* rm_k2  = (const float*)d_in[14];
    const float* rm_x3  = (const float*)d_in[15];
    const float* rm_w3  = (const float*)d_in[16];
    const float* rm_b3  = (const float*)d_in[17];
    const float* rm_x4  = (const float*)d_in[18];
    const float* rm_w4  = (const float*)d_in[19];
    const float* rm_b4  = (const float*)d_in[20];
    const float* rm_x5  = (const float*)d_in[21];
    const float* rm_w5  = (const float*)d_in[22];
    const float* rm_b5  = (const float*)d_in[23];
    float* out = (float*)d_out;

    k_init<<<1, 32>>>();
    k_pack_static<<<592, 256>>>(img, w1, w2, rm_in1, rm_k1, rm_k2);
    k_conv1<<<432, 256>>>(b1);
    k_pool1<<<1, 864>>>();
    k_pack_big<<<2048, 256>>>(rm_in2, wfc3, rm_w3, wfc4, rm_w4, wfc5, rm_w5,
                              bfc3, rm_b3, bfc4, rm_b4, bfc5, rm_b5);
    k_conv2<<<1024, 256>>>(b2);
    k_pool2<<<1, 256>>>();
    k_packx<<<32, 256>>>(rm_x3, 256, 0);
    k_fc3<<<120, 256>>>();
    k_packx<<<15, 256>>>(rm_x4, 120, 1);
    k_fc4<<<84, 128>>>();
    k_packx<<<11, 256>>>(rm_x5, 84, 2);
    k_fc5<<<10, 128>>>(out);
}